// round 16
// baseline (speedup 1.0000x reference)
#include <cuda_runtime.h>
#include <cuda_bf16.h>
#include <math.h>
#include <stdint.h>

#define TT 2048          // sequence length
#define CC 2048          // embed dim
#define HH 16            // heads
#define DD 128           // head dim
#define NBITS 7
#define RSW 12           // u32 words per row per split tile (8 used + 4 pad)
#define FIXCAP 8192
#define KT 64            // k-tile for k_fix_raw W staging
#define NPAIRS (TT * CC / 2)

#define STG 3                       // cp.async pipeline stages
#define TILEW (128 * RSW)           // u32 words per split tile
#define GEMM_DSM (STG * 4 * TILEW * 4)   // 72KB; 2 CTAs/SM = 144KB <= 228KB

// NOTE: tcgen05/TMEM is NOT usable here — the harness compiles PTX with
// .target sm_103 (no arch-specific 'a' features); ptxas rejects tcgen05.
// Legacy mma.sync is the tensor path ceiling.

// ---------------- scratch (static device globals; no allocation) ----------------
__device__ __align__(16) float g_Qraw[(size_t)TT * CC];
__device__ __align__(16) float g_Kraw[(size_t)TT * CC];
__device__ __align__(16) float g_Vraw[(size_t)TT * CC];
__device__ __align__(16) float g_S[(size_t)HH * TT * TT];   // scores (float)
__device__ int g_qc[HH * TT];
__device__ int g_kc[HH * TT];
__device__ int g_fixcnt;
__device__ int g_fixlist[FIXCAP];

// pre-split packed-bf16x2 operands (hi/lo). word w of a row = pair (2w, 2w+1)
__device__ __align__(16) uint32_t g_xh[NPAIRS],  g_xl[NPAIRS];
__device__ __align__(16) uint32_t g_Wqh[NPAIRS], g_Wql[NPAIRS];
__device__ __align__(16) uint32_t g_Wkh[NPAIRS], g_Wkl[NPAIRS];
__device__ __align__(16) uint32_t g_Wvh[NPAIRS], g_Wvl[NPAIRS];
__device__ __align__(16) uint32_t g_Wph[NPAIRS], g_Wpl[NPAIRS];
__device__ __align__(16) uint32_t g_Yh[NPAIRS],  g_Yl[NPAIRS];
__device__ __align__(16) uint32_t g_Qnh[NPAIRS], g_Qnl[NPAIRS];
__device__ __align__(16) uint32_t g_Knh[NPAIRS], g_Knl[NPAIRS];
__device__ __align__(16) uint32_t g_Vth[NPAIRS], g_Vtl[NPAIRS];
__device__ __align__(16) uint32_t g_Sh[(size_t)HH * TT * TT / 2];
__device__ __align__(16) uint32_t g_Sl[(size_t)HH * TT * TT / 2];

// ---------------- split helpers ----------------
__device__ __forceinline__ void split2(float x, float& hi, float& lo)
{
    hi = __bfloat162float(__float2bfloat16_rn(x));
    lo = x - hi;
}

__device__ __forceinline__ uint32_t pack2(float a, float b)
{
    __nv_bfloat162 t = __floats2bfloat162_rn(a, b);   // a -> low half
    return *reinterpret_cast<uint32_t*>(&t);
}

__device__ __forceinline__ uint32_t smem_u32(const void* p)
{
    uint32_t a;
    asm("{ .reg .u64 t; cvta.to.shared.u64 t, %1; cvt.u32.u64 %0, t; }" : "=r"(a) : "l"(p));
    return a;
}

__device__ __forceinline__ void ldsm_x4(uint32_t& r0, uint32_t& r1,
                                        uint32_t& r2, uint32_t& r3, uint32_t addr)
{
    asm volatile("ldmatrix.sync.aligned.m8n8.x4.shared.b16 {%0,%1,%2,%3}, [%4];"
                 : "=r"(r0), "=r"(r1), "=r"(r2), "=r"(r3) : "r"(addr));
}

__device__ __forceinline__ void cp16(uint32_t dst, const uint32_t* src)
{
    asm volatile("cp.async.cg.shared.global [%0], [%1], 16;" :: "r"(dst), "l"(src));
}

// one launch splits all 5 input matrices; dst resolved in device code
__global__ __launch_bounds__(256) void k_split_all(const float* __restrict__ x,
                                                   const float* __restrict__ Wq,
                                                   const float* __restrict__ Wk,
                                                   const float* __restrict__ Wv,
                                                   const float* __restrict__ Wp)
{
    const float* s;
    uint32_t* hd;
    uint32_t* ld;
    switch (blockIdx.y) {
        case 0: s = x;  hd = g_xh;  ld = g_xl;  break;
        case 1: s = Wq; hd = g_Wqh; ld = g_Wql; break;
        case 2: s = Wk; hd = g_Wkh; ld = g_Wkl; break;
        case 3: s = Wv; hd = g_Wvh; ld = g_Wvl; break;
        default: s = Wp; hd = g_Wph; ld = g_Wpl; break;
    }
    for (int i = blockIdx.x * 256 + threadIdx.x; i < NPAIRS; i += gridDim.x * 256) {
        float2 v = ((const float2*)s)[i];
        float h0, l0, h1, l1;
        split2(v.x, h0, l0);
        split2(v.y, h1, l1);
        hd[i] = pack2(h0, h1);
        ld[i] = pack2(l0, l1);
    }
}

__device__ __forceinline__ void mma_bf16(float d[4], const uint32_t a[4],
                                         uint32_t b0, uint32_t b1)
{
    asm volatile(
        "mma.sync.aligned.m16n8k16.row.col.f32.bf16.bf16.f32 "
        "{%0,%1,%2,%3}, {%4,%5,%6,%7}, {%8,%9}, {%0,%1,%2,%3};"
        : "+f"(d[0]), "+f"(d[1]), "+f"(d[2]), "+f"(d[3])
        : "r"(a[0]), "r"(a[1]), "r"(a[2]), "r"(a[3]), "r"(b0), "r"(b1));
}

// ============================================================
// bf16x3 GEMM core: 3-stage cp.async pipeline + ldmatrix fragments.
// B fragments loaded per n-pair (low register pressure -> 2 CTAs/SM).
// MMA ordering per accumulator is bitwise-identical to round 15.
// Dynamic smem layout: [stage][4 tiles: AH, AL, BH, BL][TILEW words].
// ============================================================
__device__ __forceinline__ void gemm_core(const uint32_t* __restrict__ Ah,
                                          const uint32_t* __restrict__ Al, int ldaw,
                                          const uint32_t* __restrict__ Bh,
                                          const uint32_t* __restrict__ Bl, int ldbw,
                                          int m0, int n0, int kend,
                                          float acc[2][8][4])
{
    extern __shared__ __align__(16) uint32_t dsm[];

    const int tid = threadIdx.x, lane = tid & 31, warp = tid >> 5;
    const int wm = (warp & 3) * 32, wn = (warp >> 2) * 64;

    const int prow = tid >> 1, pjw = (tid & 1) * 4;
    const uint32_t psmw = (uint32_t)(prow * RSW + pjw);
    const size_t aoff = (size_t)(m0 + prow) * ldaw + pjw;
    const size_t boff = (size_t)(n0 + prow) * ldbw + pjw;

    // ldmatrix per-lane offset (bytes): row = (lane&15), word = (lane>>4)*4
    const uint32_t lmoff = (((lane & 15) * RSW) + ((lane >> 4) * 4)) * 4u;

#pragma unroll
    for (int tm = 0; tm < 2; tm++)
#pragma unroll
        for (int tn = 0; tn < 8; tn++)
#pragma unroll
            for (int e = 0; e < 4; e++) acc[tm][tn][e] = 0.f;

    const int NS = kend >> 4;   // slabs of 16 bf16 (8 words)

    // issue slab s into stage stg (one commit group, always)
    auto issue_slab = [&](int s, int stg) {
        if (s < NS) {
            const int kw = s * 8;
            uint32_t base = smem_u32(dsm) + (uint32_t)(stg * 4 * TILEW) * 4u + psmw * 4u;
            cp16(base + 0u * TILEW * 4u, Ah + aoff + kw);
            cp16(base + 1u * TILEW * 4u, Al + aoff + kw);
            cp16(base + 2u * TILEW * 4u, Bh + boff + kw);
            cp16(base + 3u * TILEW * 4u, Bl + boff + kw);
        }
        asm volatile("cp.async.commit_group;" ::: "memory");
    };

    issue_slab(0, 0);
    issue_slab(1, 1);
    issue_slab(2, 2);

    int stg = 0;
    for (int s = 0; s < NS; s++) {
        asm volatile("cp.async.wait_group 2;" ::: "memory");
        __syncthreads();

        const uint32_t sbase = smem_u32(dsm) + (uint32_t)(stg * 4 * TILEW) * 4u;
        const uint32_t aH = sbase + 0u * TILEW * 4u + lmoff;
        const uint32_t aL = sbase + 1u * TILEW * 4u + lmoff;
        const uint32_t bH = sbase + 2u * TILEW * 4u + lmoff;
        const uint32_t bL = sbase + 3u * TILEW * 4u + lmoff;

        uint32_t ar[2][2][4];
#pragma unroll
        for (int tm = 0; tm < 2; tm++) {
            ldsm_x4(ar[0][tm][0], ar[0][tm][1], ar[0][tm][2], ar[0][tm][3],
                    aH + (uint32_t)((wm + 16 * tm) * RSW * 4));
            ldsm_x4(ar[1][tm][0], ar[1][tm][1], ar[1][tm][2], ar[1][tm][3],
                    aL + (uint32_t)((wm + 16 * tm) * RSW * 4));
        }

        // B fragments per n-pair: only 8 live regs -> fits 128-reg budget
#pragma unroll
        for (int p = 0; p < 4; p++) {
            uint32_t bfh[4], bfl[4];
            ldsm_x4(bfh[0], bfh[1], bfh[2], bfh[3],
                    bH + (uint32_t)((wn + 16 * p) * RSW * 4));
            ldsm_x4(bfl[0], bfl[1], bfl[2], bfl[3],
                    bL + (uint32_t)((wn + 16 * p) * RSW * 4));
#pragma unroll
            for (int o = 0; o < 2; o++) {
                const int tn = 2 * p + o;
                uint32_t bh0 = bfh[o], bh1 = bfh[o + 2];
                uint32_t bl0 = bfl[o], bl1 = bfl[o + 2];
#pragma unroll
                for (int tm = 0; tm < 2; tm++) {
                    mma_bf16(acc[tm][tn], ar[1][tm], bh0, bh1);  // lo*hi
                    mma_bf16(acc[tm][tn], ar[0][tm], bl0, bl1);  // hi*lo
                    mma_bf16(acc[tm][tn], ar[0][tm], bh0, bh1);  // hi*hi
                }
            }
        }

        __syncthreads();
        issue_slab(s + STG, stg);
        stg = (stg == STG - 1) ? 0 : stg + 1;
    }
}

__device__ __forceinline__ void epi_store(float* __restrict__ C, int ldc,
                                          int m0, int n0, float acc[2][8][4])
{
    const int lane = threadIdx.x & 31, warp = threadIdx.x >> 5;
    const int g = lane >> 2, tig = lane & 3;
    const int wm = (warp & 3) * 32, wn = (warp >> 2) * 64;
#pragma unroll
    for (int tm = 0; tm < 2; tm++)
#pragma unroll
        for (int tn = 0; tn < 8; tn++) {
            int r = m0 + wm + 16 * tm + g;
            int c = n0 + wn + 8 * tn + 2 * tig;
            *(float2*)(C + (size_t)r * ldc + c) = make_float2(acc[tm][tn][0], acc[tm][tn][1]);
            *(float2*)(C + (size_t)(r + 8) * ldc + c) = make_float2(acc[tm][tn][2], acc[tm][tn][3]);
        }
}

// epilogue writing PRE-SPLIT output (pairs (c, c+1) are contiguous in acc)
__device__ __forceinline__ void epi_store_split(uint32_t* __restrict__ Hd,
                                                uint32_t* __restrict__ Ld, int ldcw,
                                                int m0, int n0, float acc[2][8][4])
{
    const int lane = threadIdx.x & 31, warp = threadIdx.x >> 5;
    const int g = lane >> 2, tig = lane & 3;
    const int wm = (warp & 3) * 32, wn = (warp >> 2) * 64;
#pragma unroll
    for (int tm = 0; tm < 2; tm++)
#pragma unroll
        for (int tn = 0; tn < 8; tn++) {
            int r = m0 + wm + 16 * tm + g;
            int c = n0 + wn + 8 * tn + 2 * tig;      // even
            size_t w0 = (size_t)r * ldcw + (c >> 1);
            size_t w1 = (size_t)(r + 8) * ldcw + (c >> 1);
            float h0, l0, h1, l1;
            split2(acc[tm][tn][0], h0, l0);
            split2(acc[tm][tn][1], h1, l1);
            Hd[w0] = pack2(h0, h1);
            Ld[w0] = pack2(l0, l1);
            split2(acc[tm][tn][2], h0, l0);
            split2(acc[tm][tn][3], h1, l1);
            Hd[w1] = pack2(h0, h1);
            Ld[w1] = pack2(l0, l1);
        }
}

// ---------------- QKV projections ----------------
__global__ __launch_bounds__(256, 2) void k_qkv_tc()
{
    const uint32_t* Bh = (blockIdx.z == 0) ? g_Wqh : (blockIdx.z == 1) ? g_Wkh : g_Wvh;
    const uint32_t* Bl = (blockIdx.z == 0) ? g_Wql : (blockIdx.z == 1) ? g_Wkl : g_Wvl;
    float* C = (blockIdx.z == 0) ? g_Qraw : (blockIdx.z == 1) ? g_Kraw : g_Vraw;
    float acc[2][8][4];
    gemm_core(g_xh, g_xl, CC / 2, Bh, Bl, CC / 2,
              blockIdx.y * 128, blockIdx.x * 128, CC, acc);
    epi_store(C, CC, blockIdx.y * 128, blockIdx.x * 128, acc);
}

// ---------------- output projection ----------------
__global__ __launch_bounds__(256, 2) void k_proj_tc(float* __restrict__ out)
{
    float acc[2][8][4];
    gemm_core(g_Yh, g_Yl, CC / 2, g_Wph, g_Wpl, CC / 2,
              blockIdx.y * 128, blockIdx.x * 128, CC, acc);
    epi_store(out, CC, blockIdx.y * 128, blockIdx.x * 128, acc);
}

// ---------------- masked scores ----------------
__global__ __launch_bounds__(256, 2) void k_scores_tc()
{
    if (blockIdx.x > blockIdx.y) return;   // upper-triangular blocks never read
    const int h = blockIdx.z;
    const size_t hw = (size_t)h * TT * DD / 2;
    float* Sp = g_S + (size_t)h * TT * TT;
    const int m0 = blockIdx.y * 128, n0 = blockIdx.x * 128;

    float acc[2][8][4];
    gemm_core(g_Qnh + hw, g_Qnl + hw, DD / 2, g_Knh + hw, g_Knl + hw, DD / 2,
              m0, n0, DD, acc);

    const float scale = 0.08838834764831845f;  // 1/sqrt(128)
    const int lane = threadIdx.x & 31, warp = threadIdx.x >> 5;
    const int g = lane >> 2, tig = lane & 3;
    const int wm = (warp & 3) * 32, wn = (warp >> 2) * 64;
#pragma unroll
    for (int tm = 0; tm < 2; tm++) {
        int r = m0 + wm + 16 * tm + g;
        int qc0 = g_qc[h * TT + r];
        int qc1 = g_qc[h * TT + r + 8];
#pragma unroll
        for (int tn = 0; tn < 8; tn++) {
            int c = n0 + wn + 8 * tn + 2 * tig;
            int kc0 = g_kc[h * TT + c];
            int kc1 = g_kc[h * TT + c + 1];
            float v00 = (c     <= r     && qc0 == kc0) ? acc[tm][tn][0] * scale : -1e30f;
            float v01 = (c + 1 <= r     && qc0 == kc1) ? acc[tm][tn][1] * scale : -1e30f;
            float v10 = (c     <= r + 8 && qc1 == kc0) ? acc[tm][tn][2] * scale : -1e30f;
            float v11 = (c + 1 <= r + 8 && qc1 == kc1) ? acc[tm][tn][3] * scale : -1e30f;
            *(float2*)(Sp + (size_t)r * TT + c) = make_float2(v00, v01);
            *(float2*)(Sp + (size_t)(r + 8) * TT + c) = make_float2(v10, v11);
        }
    }
}

// ---------------- P @ V: writes PRE-SPLIT Y directly ----------------
__global__ __launch_bounds__(256, 2) void k_pv_tc()
{
    const int h = blockIdx.z;
    const uint32_t* Ah = g_Sh + (size_t)h * TT * TT / 2;
    const uint32_t* Al = g_Sl + (size_t)h * TT * TT / 2;
    const uint32_t* Bh = g_Vth + (size_t)h * DD * TT / 2;
    const uint32_t* Bl = g_Vtl + (size_t)h * DD * TT / 2;
    const int m0 = blockIdx.y * 128;
    const int kend = (blockIdx.y + 1) * 128;      // causal extent

    float acc[2][8][4];
    gemm_core(Ah, Al, TT / 2, Bh, Bl, TT / 2, m0, 0, kend, acc);
    epi_store_split(g_Yh, g_Yl, CC / 2, m0, h * DD, acc);
}

// ---------------- worklist counter zero ----------------
__global__ void k_zero_cnt() { g_fixcnt = 0; }

// ---------------- RoPE + RMS-norm + code + margin flag; writes SPLIT Qn/Kn ----------------
__global__ __launch_bounds__(256) void k_ropenorm(const float* __restrict__ cosb,
                                                  const float* __restrict__ sinb,
                                                  const float* __restrict__ Wdq,
                                                  const float* __restrict__ Wdk)
{
    __shared__ float srow[8][128];
    int warp = (blockIdx.x * blockDim.x + threadIdx.x) >> 5;
    int wil = (threadIdx.x >> 5);
    int lane = threadIdx.x & 31;
    int qk = warp >> 15;
    int rem = warp & 32767;
    int t = rem >> 4;
    int h = rem & 15;

    const float* src = (qk ? g_Kraw : g_Qraw) + (size_t)t * CC + h * DD;
    const float* Wd = qk ? Wdk : Wdq;

    float v0 = src[lane], v1 = src[lane + 32], v2 = src[lane + 64], v3 = src[lane + 96];
    float c0 = cosb[t * 64 + lane],      s0 = sinb[t * 64 + lane];
    float c1 = cosb[t * 64 + lane + 32], s1 = sinb[t * 64 + lane + 32];

    float r0 =  v0 * c0 + v2 * s0;
    float r1 =  v1 * c1 + v3 * s1;
    float r2 = -v0 * s0 + v2 * c0;
    float r3 = -v1 * s1 + v3 * c1;

    float ss = r0 * r0 + r1 * r1 + r2 * r2 + r3 * r3;
#pragma unroll
    for (int o = 16; o; o >>= 1) ss += __shfl_xor_sync(0xffffffffu, ss, o);
    float sc = rsqrtf(ss * (1.0f / 128.0f) + 1e-6f);
    r0 *= sc; r1 *= sc; r2 *= sc; r3 *= sc;

    srow[wil][lane] = r0; srow[wil][lane + 32] = r1;
    srow[wil][lane + 64] = r2; srow[wil][lane + 96] = r3;
    __syncwarp();
    {
        uint32_t* Hd = qk ? g_Knh : g_Qnh;
        uint32_t* Ld = qk ? g_Knl : g_Qnl;
        size_t base = ((size_t)h * TT + t) * (DD / 2);
        float a = srow[wil][2 * lane], b = srow[wil][2 * lane + 1];
        float ha, la, hb, lb;
        split2(a, ha, la); split2(b, hb, lb);
        Hd[base + lane] = pack2(ha, hb);
        Ld[base + lane] = pack2(la, lb);
        a = srow[wil][64 + 2 * lane]; b = srow[wil][64 + 2 * lane + 1];
        split2(a, ha, la); split2(b, hb, lb);
        Hd[base + 32 + lane] = pack2(ha, hb);
        Ld[base + 32 + lane] = pack2(la, lb);
    }

    int code = 0;
    float margin = 1e30f;
#pragma unroll
    for (int k = 0; k < NBITS; k++) {
        float z = r0 * Wd[k * DD + lane] + r1 * Wd[k * DD + lane + 32]
                + r2 * Wd[k * DD + lane + 64] + r3 * Wd[k * DD + lane + 96];
#pragma unroll
        for (int o = 16; o; o >>= 1) z += __shfl_xor_sync(0xffffffffu, z, o);
        float sg = 1.0f / (1.0f + expf(-z));
        float u = sg * 1.99f;
        int bit = (int)floorf(u);
        margin = fminf(margin, fabsf(u - 1.0f));
        code += bit << k;
    }
    if (lane == 0) {
        (qk ? g_kc : g_qc)[h * TT + t] = code;
        if (margin < 2e-4f) {
            int idx = atomicAdd(&g_fixcnt, 1);
            if (idx < FIXCAP) g_fixlist[idx] = (qk << 20) | (h << 16) | t;
        }
    }
}

// ---------------- exact FFMA recompute of flagged raw rows ----------------
// CRITICAL: single fp32 accumulator, fma over k ascending — the reference-
// matching ordering (rounds 2/5/7/8/9/11/12/14/15). Never change this.
__global__ __launch_bounds__(128) void k_fix_raw(const float* __restrict__ x,
                                                 const float* __restrict__ Wq,
                                                 const float* __restrict__ Wk)
{
    __shared__ float sx[CC];
    __shared__ float sW[128 * (KT + 1)];
    int b = blockIdx.x;
    int cnt = g_fixcnt;
    if (cnt > FIXCAP) cnt = FIXCAP;
    if (b >= cnt) return;
    int e = g_fixlist[b];
    int qk = (e >> 20) & 1;
    int h = (e >> 16) & 15;
    int t = e & 0xFFFF;
    const int tid = threadIdx.x;

    const float4* xr4 = (const float4*)(x + (size_t)t * CC);
    float4* sx4 = (float4*)sx;
#pragma unroll
    for (int i = 0; i < 4; i++) sx4[tid + 128 * i] = xr4[tid + 128 * i];

    const float* W = qk ? Wk : Wq;
    const float4* W4 = (const float4*)(W + (size_t)h * DD * CC);
    float* dst = (qk ? g_Kraw : g_Qraw) + (size_t)t * CC + h * DD;

    float acc = 0.f;
    for (int k0 = 0; k0 < CC; k0 += KT) {
        __syncthreads();
#pragma unroll
        for (int i = 0; i < 16; i++) {
            int slot = tid + 128 * i;
            int row = slot >> 4, c4 = slot & 15;
            float4 v = W4[(size_t)row * (CC / 4) + (k0 >> 2) + c4];
            float* p = &sW[row * (KT + 1) + c4 * 4];
            p[0] = v.x; p[1] = v.y; p[2] = v.z; p[3] = v.w;
        }
        __syncthreads();
        const float* wrow = &sW[tid * (KT + 1)];
        const float* xk = &sx[k0];
#pragma unroll
        for (int kk = 0; kk < KT; kk++)
            acc = fmaf(xk[kk], wrow[kk], acc);
    }
    dst[tid] = acc;
}

// ---------------- rope/norm/code recompute for flagged rows; writes SPLIT ----------------
__global__ __launch_bounds__(32) void k_rope_fix(const float* __restrict__ cosb,
                                                 const float* __restrict__ sinb,
                                                 const float* __restrict__ Wdq,
                                                 const float* __restrict__ Wdk)
{
    __shared__ float srow[128];
    int b = blockIdx.x;
    int cnt = g_fixcnt;
    if (cnt > FIXCAP) cnt = FIXCAP;
    if (b >= cnt) return;
    int e = g_fixlist[b];
    int qk = (e >> 20) & 1;
    int h = (e >> 16) & 15;
    int t = e & 0xFFFF;
    int lane = threadIdx.x;

    const float* src = (qk ? g_Kraw : g_Qraw) + (size_t)t * CC + h * DD;
    const float* Wd = qk ? Wdk : Wdq;

    float v0 = src[lane], v1 = src[lane + 32], v2 = src[lane + 64], v3 = src[lane + 96];
    float c0 = cosb[t * 64 + lane],      s0 = sinb[t * 64 + lane];
    float c1 = cosb[t * 64 + lane + 32], s1 = sinb[t * 64 + lane + 32];

    float r0 =  v0 * c0 + v2 * s0;
    float r1 =  v1 * c1 + v3 * s1;
    float r2 = -v0 * s0 + v2 * c0;
    float r3 = -v1 * s1 + v3 * c1;

    float ss = r0 * r0 + r1 * r1 + r2 * r2 + r3 * r3;
#pragma unroll
    for (int o = 16; o; o >>= 1) ss += __shfl_xor_sync(0xffffffffu, ss, o);
    float sc = rsqrtf(ss * (1.0f / 128.0f) + 1e-6f);
    r0 *= sc; r1 *= sc; r2 *= sc; r3 *= sc;

    srow[lane] = r0; srow[lane + 32] = r1;
    srow[lane + 64] = r2; srow[lane + 96] = r3;
    __syncwarp();
    {
        uint32_t* Hd = qk ? g_Knh : g_Qnh;
        uint32_t* Ld = qk ? g_Knl : g_Qnl;
        size_t base = ((size_t)h * TT + t) * (DD / 2);
        float a = srow[2 * lane], bb = srow[2 * lane + 1];
        float ha, la, hb, lb;
        split2(a, ha, la); split2(bb, hb, lb);
        Hd[base + lane] = pack2(ha, hb);
        Ld[base + lane] = pack2(la, lb);
        a = srow[64 + 2 * lane]; bb = srow[64 + 2 * lane + 1];
        split2(a, ha, la); split2(bb, hb, lb);
        Hd[base + 32 + lane] = pack2(ha, hb);
        Ld[base + 32 + lane] = pack2(la, lb);
    }

    int code = 0;
#pragma unroll
    for (int k = 0; k < NBITS; k++) {
        float z = r0 * Wd[k * DD + lane] + r1 * Wd[k * DD + lane + 32]
                + r2 * Wd[k * DD + lane + 64] + r3 * Wd[k * DD + lane + 96];
#pragma unroll
        for (int o = 16; o; o >>= 1) z += __shfl_xor_sync(0xffffffffu, z, o);
        float sg = 1.0f / (1.0f + expf(-z));
        int bit = (int)floorf(sg * 1.99f);
        code += bit << k;
    }
    if (lane == 0) (qk ? g_kc : g_qc)[h * TT + t] = code;
}

// ---------------- V transpose: writes PRE-SPLIT Vt directly ----------------
__global__ void k_transpose()
{
    __shared__ float tile[32][33];
    int x = blockIdx.x * 32 + threadIdx.x;
    int y = blockIdx.y * 32 + threadIdx.y;
#pragma unroll
    for (int i = 0; i < 32; i += 8)
        tile[threadIdx.y + i][threadIdx.x] = g_Vraw[(size_t)(y + i) * CC + x];
    __syncthreads();
    int tx = threadIdx.x, ty = threadIdx.y;
    if (tx < 16) {
#pragma unroll
        for (int i = 0; i < 32; i += 8) {
            int d = blockIdx.x * 32 + ty + i;              // Vt row
            float a = tile[2 * tx][ty + i];
            float b = tile[2 * tx + 1][ty + i];
            float ha, la, hb, lb;
            split2(a, ha, la); split2(b, hb, lb);
            size_t w = (size_t)d * (TT / 2) + blockIdx.y * 16 + tx;
            g_Vth[w] = pack2(ha, hb);
            g_Vtl[w] = pack2(la, lb);
        }
    }
}

// ---------------- row softmax: reads float S, writes PRE-SPLIT weights ----------------
__global__ __launch_bounds__(128) void k_softmax()
{
    int row = blockIdx.x;          // h*T + q
    int h = row >> 11;
    int q = row & 2047;
    const float* S = g_S + (size_t)h * TT * TT + (size_t)q * TT;
    size_t rowbase_w = ((size_t)h * TT * TT + (size_t)q * TT) >> 1;
    int jmaxw = (((q >> 7) + 1) << 7) >> 1;   // word extent (pairs)
    int tid = threadIdx.x;

    __shared__ float smax[4];
    __shared__ float ssum[4];

    float2 sv[8];
    int cnt = 0;
    float m = -1e30f;
    for (int jw = tid; jw < jmaxw; jw += 128) {
        float2 s = ((const float2*)S)[jw];
        sv[cnt++] = s;
        m = fmaxf(m, fmaxf(s.x, s.y));
    }
#pragma unroll
    for (int o = 16; o; o >>= 1) m = fmaxf(m, __shfl_xor_sync(0xffffffffu, m, o));
    if ((tid & 31) == 0) smax[tid >> 5] = m;
    __syncthreads();
    m = fmaxf(fmaxf(smax[0], smax[1]), fmaxf(smax[2], smax[3]));

    if (m <= -1e29f) {
        for (int jw = tid; jw < jmaxw; jw += 128) {
            g_Sh[rowbase_w + jw] = 0u;
            g_Sl[rowbase_w + jw] = 0u;
        }
        return;
    }

    float sum = 0.f;
    cnt = 0;
    float2 ev[8];
    for (int jw = tid; jw < jmaxw; jw += 128) {
        float e0 = expf(sv[cnt].x - m);
        float e1 = expf(sv[cnt].y - m);
        ev[cnt] = make_float2(e0, e1);
        cnt++;
        sum += e0 + e1;
    }
#pragma unroll
    for (int o = 16; o; o >>= 1) sum += __shfl_xor_sync(0xffffffffu, sum, o);
    if ((tid & 31) == 0) ssum[tid >> 5] = sum;
    __syncthreads();
    sum = ssum[0] + ssum[1] + ssum[2] + ssum[3];

    float inv = 1.0f / sum;
    cnt = 0;
    for (int jw = tid; jw < jmaxw; jw += 128) {
        float w0 = ev[cnt].x * inv;
        float w1 = ev[cnt].y * inv;
        cnt++;
        float h0, l0, h1, l1;
        split2(w0, h0, l0);
        split2(w1, h1, l1);
        g_Sh[rowbase_w + jw] = pack2(h0, h1);
        g_Sl[rowbase_w + jw] = pack2(l0, l1);
    }
}

// ---------------- launch ----------------
extern "C" void kernel_launch(void* const* d_in, const int* in_sizes, int n_in,
                              void* d_out, int out_size)
{
    const float* x     = (const float*)d_in[0];
    const float* cosb  = (const float*)d_in[1];
    const float* sinb  = (const float*)d_in[2];
    const float* Wq    = (const float*)d_in[3];
    const float* Wk    = (const float*)d_in[4];
    const float* Wv    = (const float*)d_in[5];
    const float* Wproj = (const float*)d_in[6];
    const float* Wdq   = (const float*)d_in[7];
    const float* Wdk   = (const float*)d_in[8];
    float* out = (float*)d_out;

    static int s_attr_done = 0;
    if (!s_attr_done) {
        cudaFuncSetAttribute(k_qkv_tc,    cudaFuncAttributeMaxDynamicSharedMemorySize, GEMM_DSM);
        cudaFuncSetAttribute(k_proj_tc,   cudaFuncAttributeMaxDynamicSharedMemorySize, GEMM_DSM);
        cudaFuncSetAttribute(k_scores_tc, cudaFuncAttributeMaxDynamicSharedMemorySize, GEMM_DSM);
        cudaFuncSetAttribute(k_pv_tc,     cudaFuncAttributeMaxDynamicSharedMemorySize, GEMM_DSM);
        s_attr_done = 1;
    }

    k_zero_cnt<<<1, 1>>>();

    k_split_all<<<dim3(512, 5), 256>>>(x, Wq, Wk, Wv, Wproj);

    k_qkv_tc<<<dim3(16, 16, 3), 256, GEMM_DSM>>>();

    k_ropenorm<<<(2 * TT * HH) / 8, 256>>>(cosb, sinb, Wdq, Wdk);
    k_fix_raw<<<FIXCAP, 128>>>(x, Wq, Wk);
    k_rope_fix<<<FIXCAP, 32>>>(cosb, sinb, Wdq, Wdk);

    k_transpose<<<dim3(64, 64), dim3(32, 8)>>>();

    k_scores_tc<<<dim3(16, 16, HH), 256, GEMM_DSM>>>();
    k_softmax<<<HH * TT, 128>>>();
    k_pv_tc<<<dim3(1, 16, HH), 256, GEMM_DSM>>>();

    k_proj_tc<<<dim3(16, 16, 1), 256, GEMM_DSM>>>(out);
}

// round 17
// speedup vs baseline: 1.1260x; 1.1260x over previous
#include <cuda_runtime.h>
#include <cuda_bf16.h>
#include <math.h>
#include <stdint.h>

#define TT 2048
#define CC 2048
#define HH 16
#define DD 128
#define NBITS 7
#define RSW 12
#define FIXCAP 8192
#define KT 64
#define NPAIRS (TT * CC / 2)

#define STG 3
#define TILEW (128 * RSW)
#define GEMM_DSM (STG * 4 * TILEW * 4)

// flash kernel smem: Q(hi,lo) + P(hi,lo) @128x68 words + 4-stage x2-tile ring + 512 red
#define QW (128 * 68)
#define FLASH_DSM ((4 * QW + 4 * 2 * TILEW + 512) * 4)

// NOTE: tcgen05/TMEM unusable (harness PTX target sm_103 lacks 'a' features).

__device__ __align__(16) float g_Qraw[(size_t)TT * CC];
__device__ __align__(16) float g_Kraw[(size_t)TT * CC];
__device__ __align__(16) float g_Vraw[(size_t)TT * CC];
__device__ int g_qc[HH * TT];
__device__ int g_kc[HH * TT];
__device__ int g_fixcnt;
__device__ int g_fixlist[FIXCAP];

__device__ __align__(16) uint32_t g_xh[NPAIRS],  g_xl[NPAIRS];
__device__ __align__(16) uint32_t g_Wqh[NPAIRS], g_Wql[NPAIRS];
__device__ __align__(16) uint32_t g_Wkh[NPAIRS], g_Wkl[NPAIRS];
__device__ __align__(16) uint32_t g_Wvh[NPAIRS], g_Wvl[NPAIRS];
__device__ __align__(16) uint32_t g_Wph[NPAIRS], g_Wpl[NPAIRS];
__device__ __align__(16) uint32_t g_Yh[NPAIRS],  g_Yl[NPAIRS];
__device__ __align__(16) uint32_t g_Qnh[NPAIRS], g_Qnl[NPAIRS];
__device__ __align__(16) uint32_t g_Knh[NPAIRS], g_Knl[NPAIRS];
__device__ __align__(16) uint32_t g_Vth[NPAIRS], g_Vtl[NPAIRS];

__device__ __forceinline__ void split2(float x, float& hi, float& lo)
{
    hi = __bfloat162float(__float2bfloat16_rn(x));
    lo = x - hi;
}
__device__ __forceinline__ uint32_t pack2(float a, float b)
{
    __nv_bfloat162 t = __floats2bfloat162_rn(a, b);
    return *reinterpret_cast<uint32_t*>(&t);
}
__device__ __forceinline__ uint32_t smem_u32(const void* p)
{
    uint32_t a;
    asm("{ .reg .u64 t; cvta.to.shared.u64 t, %1; cvt.u32.u64 %0, t; }" : "=r"(a) : "l"(p));
    return a;
}
__device__ __forceinline__ void ldsm_x4(uint32_t& r0, uint32_t& r1,
                                        uint32_t& r2, uint32_t& r3, uint32_t addr)
{
    asm volatile("ldmatrix.sync.aligned.m8n8.x4.shared.b16 {%0,%1,%2,%3}, [%4];"
                 : "=r"(r0), "=r"(r1), "=r"(r2), "=r"(r3) : "r"(addr));
}
__device__ __forceinline__ void cp16(uint32_t dst, const uint32_t* src)
{
    asm volatile("cp.async.cg.shared.global [%0], [%1], 16;" :: "r"(dst), "l"(src));
}

__global__ __launch_bounds__(256) void k_split_all(const float* __restrict__ x,
                                                   const float* __restrict__ Wq,
                                                   const float* __restrict__ Wk,
                                                   const float* __restrict__ Wv,
                                                   const float* __restrict__ Wp)
{
    const float* s;
    uint32_t* hd;
    uint32_t* ld;
    switch (blockIdx.y) {
        case 0: s = x;  hd = g_xh;  ld = g_xl;  break;
        case 1: s = Wq; hd = g_Wqh; ld = g_Wql; break;
        case 2: s = Wk; hd = g_Wkh; ld = g_Wkl; break;
        case 3: s = Wv; hd = g_Wvh; ld = g_Wvl; break;
        default: s = Wp; hd = g_Wph; ld = g_Wpl; break;
    }
    for (int i = blockIdx.x * 256 + threadIdx.x; i < NPAIRS; i += gridDim.x * 256) {
        float2 v = ((const float2*)s)[i];
        float h0, l0, h1, l1;
        split2(v.x, h0, l0);
        split2(v.y, h1, l1);
        hd[i] = pack2(h0, h1);
        ld[i] = pack2(l0, l1);
    }
}

__device__ __forceinline__ void mma_bf16(float d[4], const uint32_t a[4],
                                         uint32_t b0, uint32_t b1)
{
    asm volatile(
        "mma.sync.aligned.m16n8k16.row.col.f32.bf16.bf16.f32 "
        "{%0,%1,%2,%3}, {%4,%5,%6,%7}, {%8,%9}, {%0,%1,%2,%3};"
        : "+f"(d[0]), "+f"(d[1]), "+f"(d[2]), "+f"(d[3])
        : "r"(a[0]), "r"(a[1]), "r"(a[2]), "r"(a[3]), "r"(b0), "r"(b1));
}

// ---------------- dense GEMM core (round-15 proven form) ----------------
__device__ __forceinline__ void gemm_core(const uint32_t* __restrict__ Ah,
                                          const uint32_t* __restrict__ Al, int ldaw,
                                          const uint32_t* __restrict__ Bh,
                                          const uint32_t* __restrict__ Bl, int ldbw,
                                          int m0, int n0, int kend,
                                          float acc[2][8][4])
{
    extern __shared__ __align__(16) uint32_t dsm[];

    const int tid = threadIdx.x, lane = tid & 31, warp = tid >> 5;
    const int wm = (warp & 3) * 32, wn = (warp >> 2) * 64;
    const int prow = tid >> 1, pjw = (tid & 1) * 4;
    const uint32_t psmw = (uint32_t)(prow * RSW + pjw);
    const size_t aoff = (size_t)(m0 + prow) * ldaw + pjw;
    const size_t boff = (size_t)(n0 + prow) * ldbw + pjw;
    const uint32_t lmoff = (((lane & 15) * RSW) + ((lane >> 4) * 4)) * 4u;

#pragma unroll
    for (int tm = 0; tm < 2; tm++)
#pragma unroll
        for (int tn = 0; tn < 8; tn++)
#pragma unroll
            for (int e = 0; e < 4; e++) acc[tm][tn][e] = 0.f;

    const int NS = kend >> 4;
    auto issue_slab = [&](int s, int stg) {
        if (s < NS) {
            const int kw = s * 8;
            uint32_t base = smem_u32(dsm) + (uint32_t)(stg * 4 * TILEW) * 4u + psmw * 4u;
            cp16(base + 0u * TILEW * 4u, Ah + aoff + kw);
            cp16(base + 1u * TILEW * 4u, Al + aoff + kw);
            cp16(base + 2u * TILEW * 4u, Bh + boff + kw);
            cp16(base + 3u * TILEW * 4u, Bl + boff + kw);
        }
        asm volatile("cp.async.commit_group;" ::: "memory");
    };

    issue_slab(0, 0);
    issue_slab(1, 1);
    issue_slab(2, 2);

    int stg = 0;
    for (int s = 0; s < NS; s++) {
        asm volatile("cp.async.wait_group 2;" ::: "memory");
        __syncthreads();

        const uint32_t sbase = smem_u32(dsm) + (uint32_t)(stg * 4 * TILEW) * 4u;
        const uint32_t aH = sbase + 0u * TILEW * 4u + lmoff;
        const uint32_t aL = sbase + 1u * TILEW * 4u + lmoff;
        const uint32_t bH = sbase + 2u * TILEW * 4u + lmoff;
        const uint32_t bL = sbase + 3u * TILEW * 4u + lmoff;

        uint32_t ar[2][2][4];
#pragma unroll
        for (int tm = 0; tm < 2; tm++) {
            ldsm_x4(ar[0][tm][0], ar[0][tm][1], ar[0][tm][2], ar[0][tm][3],
                    aH + (uint32_t)((wm + 16 * tm) * RSW * 4));
            ldsm_x4(ar[1][tm][0], ar[1][tm][1], ar[1][tm][2], ar[1][tm][3],
                    aL + (uint32_t)((wm + 16 * tm) * RSW * 4));
        }
        uint32_t bf[2][4][4];
#pragma unroll
        for (int p = 0; p < 4; p++) {
            ldsm_x4(bf[0][p][0], bf[0][p][1], bf[0][p][2], bf[0][p][3],
                    bH + (uint32_t)((wn + 16 * p) * RSW * 4));
            ldsm_x4(bf[1][p][0], bf[1][p][1], bf[1][p][2], bf[1][p][3],
                    bL + (uint32_t)((wn + 16 * p) * RSW * 4));
        }
#pragma unroll
        for (int tn = 0; tn < 8; tn++) {
            const int p = tn >> 1, o = tn & 1;
            uint32_t bh0 = bf[0][p][o], bh1 = bf[0][p][o + 2];
            uint32_t bl0 = bf[1][p][o], bl1 = bf[1][p][o + 2];
#pragma unroll
            for (int tm = 0; tm < 2; tm++) {
                mma_bf16(acc[tm][tn], ar[1][tm], bh0, bh1);
                mma_bf16(acc[tm][tn], ar[0][tm], bl0, bl1);
                mma_bf16(acc[tm][tn], ar[0][tm], bh0, bh1);
            }
        }
        __syncthreads();
        issue_slab(s + STG, stg);
        stg = (stg == STG - 1) ? 0 : stg + 1;
    }
}

__device__ __forceinline__ void epi_store(float* __restrict__ C, int ldc,
                                          int m0, int n0, float acc[2][8][4])
{
    const int lane = threadIdx.x & 31, warp = threadIdx.x >> 5;
    const int g = lane >> 2, tig = lane & 3;
    const int wm = (warp & 3) * 32, wn = (warp >> 2) * 64;
#pragma unroll
    for (int tm = 0; tm < 2; tm++)
#pragma unroll
        for (int tn = 0; tn < 8; tn++) {
            int r = m0 + wm + 16 * tm + g;
            int c = n0 + wn + 8 * tn + 2 * tig;
            *(float2*)(C + (size_t)r * ldc + c) = make_float2(acc[tm][tn][0], acc[tm][tn][1]);
            *(float2*)(C + (size_t)(r + 8) * ldc + c) = make_float2(acc[tm][tn][2], acc[tm][tn][3]);
        }
}

__global__ __launch_bounds__(256, 1) void k_qkv_tc()
{
    const uint32_t* Bh = (blockIdx.z == 0) ? g_Wqh : (blockIdx.z == 1) ? g_Wkh : g_Wvh;
    const uint32_t* Bl = (blockIdx.z == 0) ? g_Wql : (blockIdx.z == 1) ? g_Wkl : g_Wvl;
    float* C = (blockIdx.z == 0) ? g_Qraw : (blockIdx.z == 1) ? g_Kraw : g_Vraw;
    float acc[2][8][4];
    gemm_core(g_xh, g_xl, CC / 2, Bh, Bl, CC / 2,
              blockIdx.y * 128, blockIdx.x * 128, CC, acc);
    epi_store(C, CC, blockIdx.y * 128, blockIdx.x * 128, acc);
}

__global__ __launch_bounds__(256, 1) void k_proj_tc(float* __restrict__ out)
{
    float acc[2][8][4];
    gemm_core(g_Yh, g_Yl, CC / 2, g_Wph, g_Wpl, CC / 2,
              blockIdx.y * 128, blockIdx.x * 128, CC, acc);
    epi_store(out, CC, blockIdx.y * 128, blockIdx.x * 128, acc);
}

// ============================================================
// FUSED flash attention: scores + online softmax + PV.
// Block = (head h = blockIdx.x, q-block qb = 15 - blockIdx.y).
// Q tile resident in smem; unified K/V cp.async ring (4 stages).
// Writes pre-split Y. Mask bits (codes) computed elsewhere.
// ============================================================
__global__ __launch_bounds__(256, 1) void k_flash()
{
    extern __shared__ __align__(16) uint32_t dsm[];
    const int h = blockIdx.x;
    const int qb = 15 - (int)blockIdx.y;
    const int m0 = qb * 128;
    const int tid = threadIdx.x, lane = tid & 31, warp = tid >> 5;
    const int g = lane >> 2, tig = lane & 3;
    const int wm = (warp & 3) * 32, wh = warp >> 2, wn = wh * 64;

    uint32_t* sQh = dsm;
    uint32_t* sQl = dsm + QW;
    uint32_t* sPh = dsm + 2 * QW;
    uint32_t* sPl = dsm + 3 * QW;
    uint32_t* ring = dsm + 4 * QW;
    float* redm = (float*)(ring + 4 * 2 * TILEW);   // [2][128]
    float* redl = redm + 256;                        // [2][128]

    // load Q tile (64 words/row) into 68-stride smem
    {
        const uint32_t* Qh = g_Qnh + ((size_t)h * TT + m0) * 64;
        const uint32_t* Ql = g_Qnl + ((size_t)h * TT + m0) * 64;
        for (int i = tid; i < 128 * 16; i += 256) {
            int r = i >> 4, w4 = (i & 15) * 4;
            *(uint4*)(sQh + r * 68 + w4) = *(const uint4*)(Qh + r * 64 + w4);
            *(uint4*)(sQl + r * 68 + w4) = *(const uint4*)(Ql + r * 64 + w4);
        }
    }

    int qcv[2][2];
#pragma unroll
    for (int tm = 0; tm < 2; tm++)
#pragma unroll
        for (int hf = 0; hf < 2; hf++)
            qcv[tm][hf] = g_qc[h * TT + m0 + wm + 16 * tm + 8 * hf + g];

    float accO[2][8][4];
#pragma unroll
    for (int tm = 0; tm < 2; tm++)
#pragma unroll
        for (int tn = 0; tn < 8; tn++)
#pragma unroll
            for (int e = 0; e < 4; e++) accO[tm][tn][e] = 0.f;
    float mrow[2][2] = {{-1e30f, -1e30f}, {-1e30f, -1e30f}};
    float lrow[2][2] = {{0.f, 0.f}, {0.f, 0.f}};

    const int NSLAB = (qb + 1) * 16;
    const int prow = tid >> 1, pjw = (tid & 1) * 4;
    const uint32_t ringb = smem_u32(ring);
    const uint32_t lm12 = (((lane & 15) * RSW) + ((lane >> 4) * 4)) * 4u;
    const uint32_t lm68 = (((lane & 15) * 68) + ((lane >> 4) * 4)) * 4u;
    const uint32_t qbase = smem_u32(sQh);
    const uint32_t pbase = smem_u32(sPh);

    auto issue = [&](int j) {
        if (j < NSLAB) {
            int kb = j >> 4, phv = (j >> 3) & 1, s = j & 7;
            uint32_t dst = ringb + (uint32_t)(((j & 3) * 2 * TILEW) + prow * RSW + pjw) * 4u;
            if (phv == 0) {
                size_t o = ((size_t)h * TT + kb * 128 + prow) * 64 + s * 8 + pjw;
                cp16(dst, g_Knh + o);
                cp16(dst + TILEW * 4u, g_Knl + o);
            } else {
                size_t o = ((size_t)h * 128 + prow) * (TT / 2) + kb * 64 + s * 8 + pjw;
                cp16(dst, g_Vth + o);
                cp16(dst + TILEW * 4u, g_Vtl + o);
            }
        }
        asm volatile("cp.async.commit_group;" ::: "memory");
    };

    issue(0); issue(1); issue(2); issue(3);
    int j = 0;
    const float scale = 0.08838834764831845f;   // 1/sqrt(128)

    for (int kb = 0; kb <= qb; kb++) {
        float accS[2][8][4];
#pragma unroll
        for (int tm = 0; tm < 2; tm++)
#pragma unroll
            for (int tn = 0; tn < 8; tn++)
#pragma unroll
                for (int e = 0; e < 4; e++) accS[tm][tn][e] = 0.f;

        // ---- QK over 8 slabs ----
        for (int s = 0; s < 8; s++, j++) {
            asm volatile("cp.async.wait_group 3;" ::: "memory");
            __syncthreads();
            uint32_t bb = ringb + (uint32_t)((j & 3) * 2 * TILEW) * 4u + lm12;
            uint32_t ar[2][2][4];
#pragma unroll
            for (int tm = 0; tm < 2; tm++) {
                uint32_t a = qbase + (uint32_t)((wm + 16 * tm) * 68 + s * 8) * 4u + lm68;
                ldsm_x4(ar[0][tm][0], ar[0][tm][1], ar[0][tm][2], ar[0][tm][3], a);
                ldsm_x4(ar[1][tm][0], ar[1][tm][1], ar[1][tm][2], ar[1][tm][3], a + QW * 4u);
            }
#pragma unroll
            for (int p = 0; p < 4; p++) {
                uint32_t bfh[4], bfl[4];
                ldsm_x4(bfh[0], bfh[1], bfh[2], bfh[3], bb + (uint32_t)((wn + 16 * p) * RSW * 4));
                ldsm_x4(bfl[0], bfl[1], bfl[2], bfl[3],
                        bb + TILEW * 4u + (uint32_t)((wn + 16 * p) * RSW * 4));
#pragma unroll
                for (int o = 0; o < 2; o++) {
                    const int tn = 2 * p + o;
#pragma unroll
                    for (int tm = 0; tm < 2; tm++) {
                        mma_bf16(accS[tm][tn], ar[1][tm], bfh[o], bfh[o + 2]);
                        mma_bf16(accS[tm][tn], ar[0][tm], bfl[o], bfl[o + 2]);
                        mma_bf16(accS[tm][tn], ar[0][tm], bfh[o], bfh[o + 2]);
                    }
                }
            }
            __syncthreads();
            issue(j + 4);
        }

        // ---- mask + scale ----
#pragma unroll
        for (int tm = 0; tm < 2; tm++) {
            int r1 = m0 + wm + 16 * tm + g;
            int r2 = r1 + 8;
#pragma unroll
            for (int tn = 0; tn < 8; tn++) {
                int c = kb * 128 + wn + 8 * tn + 2 * tig;
                int kc0 = g_kc[h * TT + c];
                int kc1 = g_kc[h * TT + c + 1];
                accS[tm][tn][0] = (c     <= r1 && qcv[tm][0] == kc0) ? accS[tm][tn][0] * scale : -1e30f;
                accS[tm][tn][1] = (c + 1 <= r1 && qcv[tm][0] == kc1) ? accS[tm][tn][1] * scale : -1e30f;
                accS[tm][tn][2] = (c     <= r2 && qcv[tm][1] == kc0) ? accS[tm][tn][2] * scale : -1e30f;
                accS[tm][tn][3] = (c + 1 <= r2 && qcv[tm][1] == kc1) ? accS[tm][tn][3] * scale : -1e30f;
            }
        }

        // ---- row max (quad shfl + cross-warp smem) ----
#pragma unroll
        for (int tm = 0; tm < 2; tm++)
#pragma unroll
            for (int hf = 0; hf < 2; hf++) {
                float lm = -1e30f;
#pragma unroll
                for (int tn = 0; tn < 8; tn++)
                    lm = fmaxf(lm, fmaxf(accS[tm][tn][2 * hf], accS[tm][tn][2 * hf + 1]));
                lm = fmaxf(lm, __shfl_xor_sync(0xffffffffu, lm, 1));
                lm = fmaxf(lm, __shfl_xor_sync(0xffffffffu, lm, 2));
                if (tig == 0) redm[wh * 128 + wm + 16 * tm + 8 * hf + g] = lm;
            }
        __syncthreads();

        float rf[2][2];
#pragma unroll
        for (int tm = 0; tm < 2; tm++)
#pragma unroll
            for (int hf = 0; hf < 2; hf++) {
                int rl = wm + 16 * tm + 8 * hf + g;
                float tmax = fmaxf(redm[rl], redm[128 + rl]);
                float mn = fmaxf(mrow[tm][hf], tmax);
                rf[tm][hf] = expf(mrow[tm][hf] - mn);   // -1e30 cases -> 0 or 1, safe
                mrow[tm][hf] = mn;
            }
#pragma unroll
        for (int tm = 0; tm < 2; tm++)
#pragma unroll
            for (int tn = 0; tn < 8; tn++) {
                accO[tm][tn][0] *= rf[tm][0];
                accO[tm][tn][1] *= rf[tm][0];
                accO[tm][tn][2] *= rf[tm][1];
                accO[tm][tn][3] *= rf[tm][1];
            }

        // ---- P = exp(s - m), sums, P split to smem ----
        float ls[2][2] = {{0.f, 0.f}, {0.f, 0.f}};
#pragma unroll
        for (int tm = 0; tm < 2; tm++) {
            int r1 = wm + 16 * tm + g, r2 = r1 + 8;
#pragma unroll
            for (int tn = 0; tn < 8; tn++) {
                float p0 = accS[tm][tn][0] <= -1e29f ? 0.f : expf(accS[tm][tn][0] - mrow[tm][0]);
                float p1 = accS[tm][tn][1] <= -1e29f ? 0.f : expf(accS[tm][tn][1] - mrow[tm][0]);
                float p2 = accS[tm][tn][2] <= -1e29f ? 0.f : expf(accS[tm][tn][2] - mrow[tm][1]);
                float p3 = accS[tm][tn][3] <= -1e29f ? 0.f : expf(accS[tm][tn][3] - mrow[tm][1]);
                ls[tm][0] += p0 + p1;
                ls[tm][1] += p2 + p3;
                int wc = wh * 32 + 4 * tn + tig;
                float ha, la, hb, lb;
                split2(p0, ha, la); split2(p1, hb, lb);
                sPh[r1 * 68 + wc] = pack2(ha, hb);
                sPl[r1 * 68 + wc] = pack2(la, lb);
                split2(p2, ha, la); split2(p3, hb, lb);
                sPh[r2 * 68 + wc] = pack2(ha, hb);
                sPl[r2 * 68 + wc] = pack2(la, lb);
            }
        }
#pragma unroll
        for (int tm = 0; tm < 2; tm++)
#pragma unroll
            for (int hf = 0; hf < 2; hf++) {
                float v = ls[tm][hf];
                v += __shfl_xor_sync(0xffffffffu, v, 1);
                v += __shfl_xor_sync(0xffffffffu, v, 2);
                if (tig == 0) redl[wh * 128 + wm + 16 * tm + 8 * hf + g] = v;
            }
        __syncthreads();   // publishes P and redl
#pragma unroll
        for (int tm = 0; tm < 2; tm++)
#pragma unroll
            for (int hf = 0; hf < 2; hf++) {
                int rl = wm + 16 * tm + 8 * hf + g;
                lrow[tm][hf] = lrow[tm][hf] * rf[tm][hf] + redl[rl] + redl[128 + rl];
            }

        // ---- PV over 8 slabs ----
        for (int s = 0; s < 8; s++, j++) {
            asm volatile("cp.async.wait_group 3;" ::: "memory");
            __syncthreads();
            uint32_t bb = ringb + (uint32_t)((j & 3) * 2 * TILEW) * 4u + lm12;
            uint32_t ar[2][2][4];
#pragma unroll
            for (int tm = 0; tm < 2; tm++) {
                uint32_t a = pbase + (uint32_t)((wm + 16 * tm) * 68 + s * 8) * 4u + lm68;
                ldsm_x4(ar[0][tm][0], ar[0][tm][1], ar[0][tm][2], ar[0][tm][3], a);
                ldsm_x4(ar[1][tm][0], ar[1][tm][1], ar[1][tm][2], ar[1][tm][3], a + QW * 4u);
            }
#pragma unroll
            for (int p = 0; p < 4; p++) {
                uint32_t bfh[4], bfl[4];
                ldsm_x4(bfh[0], bfh[1], bfh[2], bfh[3], bb + (uint32_t)((wn + 16 * p) * RSW * 4));
                ldsm_x4(bfl[0], bfl[1], bfl[2], bfl[3],
                        bb + TILEW * 4u + (uint32_t)((wn + 16 * p) * RSW * 4));
#pragma unroll
                for (int o = 0; o < 2; o++) {
                    const int tn = 2 * p + o;
#pragma unroll
                    for (int tm = 0; tm < 2; tm++) {
                        mma_bf16(accO[tm][tn], ar[1][tm], bfh[o], bfh[o + 2]);
                        mma_bf16(accO[tm][tn], ar[0][tm], bfl[o], bfl[o + 2]);
                        mma_bf16(accO[tm][tn], ar[0][tm], bfh[o], bfh[o + 2]);
                    }
                }
            }
            __syncthreads();
            issue(j + 4);
        }
    }

    // ---- epilogue: O/l -> pre-split Y ----
    float inv[2][2];
#pragma unroll
    for (int tm = 0; tm < 2; tm++)
#pragma unroll
        for (int hf = 0; hf < 2; hf++)
            inv[tm][hf] = lrow[tm][hf] > 0.f ? 1.0f / lrow[tm][hf] : 0.f;

#pragma unroll
    for (int tm = 0; tm < 2; tm++) {
        int r1 = m0 + wm + 16 * tm + g;
        int r2 = r1 + 8;
#pragma unroll
        for (int tn = 0; tn < 8; tn++) {
            int wc = h * 64 + wh * 32 + 4 * tn + tig;
            float ha, la, hb, lb;
            split2(accO[tm][tn][0] * inv[tm][0], ha, la);
            split2(accO[tm][tn][1] * inv[tm][0], hb, lb);
            g_Yh[(size_t)r1 * (CC / 2) + wc] = pack2(ha, hb);
            g_Yl[(size_t)r1 * (CC / 2) + wc] = pack2(la, lb);
            split2(accO[tm][tn][2] * inv[tm][1], ha, la);
            split2(accO[tm][tn][3] * inv[tm][1], hb, lb);
            g_Yh[(size_t)r2 * (CC / 2) + wc] = pack2(ha, hb);
            g_Yl[(size_t)r2 * (CC / 2) + wc] = pack2(la, lb);
        }
    }
}

__global__ void k_zero_cnt() { g_fixcnt = 0; }

__global__ __launch_bounds__(256) void k_ropenorm(const float* __restrict__ cosb,
                                                  const float* __restrict__ sinb,
                                                  const float* __restrict__ Wdq,
                                                  const float* __restrict__ Wdk)
{
    __shared__ float srow[8][128];
    int warp = (blockIdx.x * blockDim.x + threadIdx.x) >> 5;
    int wil = (threadIdx.x >> 5);
    int lane = threadIdx.x & 31;
    int qk = warp >> 15;
    int rem = warp & 32767;
    int t = rem >> 4;
    int h = rem & 15;

    const float* src = (qk ? g_Kraw : g_Qraw) + (size_t)t * CC + h * DD;
    const float* Wd = qk ? Wdk : Wdq;

    float v0 = src[lane], v1 = src[lane + 32], v2 = src[lane + 64], v3 = src[lane + 96];
    float c0 = cosb[t * 64 + lane],      s0 = sinb[t * 64 + lane];
    float c1 = cosb[t * 64 + lane + 32], s1 = sinb[t * 64 + lane + 32];

    float r0 =  v0 * c0 + v2 * s0;
    float r1 =  v1 * c1 + v3 * s1;
    float r2 = -v0 * s0 + v2 * c0;
    float r3 = -v1 * s1 + v3 * c1;

    float ss = r0 * r0 + r1 * r1 + r2 * r2 + r3 * r3;
#pragma unroll
    for (int o = 16; o; o >>= 1) ss += __shfl_xor_sync(0xffffffffu, ss, o);
    float sc = rsqrtf(ss * (1.0f / 128.0f) + 1e-6f);
    r0 *= sc; r1 *= sc; r2 *= sc; r3 *= sc;

    srow[wil][lane] = r0; srow[wil][lane + 32] = r1;
    srow[wil][lane + 64] = r2; srow[wil][lane + 96] = r3;
    __syncwarp();
    {
        uint32_t* Hd = qk ? g_Knh : g_Qnh;
        uint32_t* Ld = qk ? g_Knl : g_Qnl;
        size_t base = ((size_t)h * TT + t) * (DD / 2);
        float a = srow[wil][2 * lane], b = srow[wil][2 * lane + 1];
        float ha, la, hb, lb;
        split2(a, ha, la); split2(b, hb, lb);
        Hd[base + lane] = pack2(ha, hb);
        Ld[base + lane] = pack2(la, lb);
        a = srow[wil][64 + 2 * lane]; b = srow[wil][64 + 2 * lane + 1];
        split2(a, ha, la); split2(b, hb, lb);
        Hd[base + 32 + lane] = pack2(ha, hb);
        Ld[base + 32 + lane] = pack2(la, lb);
    }

    int code = 0;
    float margin = 1e30f;
#pragma unroll
    for (int k = 0; k < NBITS; k++) {
        float z = r0 * Wd[k * DD + lane] + r1 * Wd[k * DD + lane + 32]
                + r2 * Wd[k * DD + lane + 64] + r3 * Wd[k * DD + lane + 96];
#pragma unroll
        for (int o = 16; o; o >>= 1) z += __shfl_xor_sync(0xffffffffu, z, o);
        float sg = 1.0f / (1.0f + expf(-z));
        float u = sg * 1.99f;
        int bit = (int)floorf(u);
        margin = fminf(margin, fabsf(u - 1.0f));
        code += bit << k;
    }
    if (lane == 0) {
        (qk ? g_kc : g_qc)[h * TT + t] = code;
        if (margin < 2e-4f) {
            int idx = atomicAdd(&g_fixcnt, 1);
            if (idx < FIXCAP) g_fixlist[idx] = (qk << 20) | (h << 16) | t;
        }
    }
}

// CRITICAL: single fp32 accumulator, fma over k ascending — reference order.
__global__ __launch_bounds__(128) void k_fix_raw(const float* __restrict__ x,
                                                 const float* __restrict__ Wq,
                                                 const float* __restrict__ Wk)
{
    __shared__ float sx[CC];
    __shared__ float sW[128 * (KT + 1)];
    int b = blockIdx.x;
    int cnt = g_fixcnt;
    if (cnt > FIXCAP) cnt = FIXCAP;
    if (b >= cnt) return;
    int e = g_fixlist[b];
    int qk = (e >> 20) & 1;
    int h = (e >> 16) & 15;
    int t = e & 0xFFFF;
    const int tid = threadIdx.x;

    const float4* xr4 = (const float4*)(x + (size_t)t * CC);
    float4* sx4 = (float4*)sx;
#pragma unroll
    for (int i = 0; i < 4; i++) sx4[tid + 128 * i] = xr4[tid + 128 * i];

    const float* W = qk ? Wk : Wq;
    const float4* W4 = (const float4*)(W + (size_t)h * DD * CC);
    float* dst = (qk ? g_Kraw : g_Qraw) + (size_t)t * CC + h * DD;

    float acc = 0.f;
    for (int k0 = 0; k0 < CC; k0 += KT) {
        __syncthreads();
#pragma unroll
        for (int i = 0; i < 16; i++) {
            int slot = tid + 128 * i;
            int row = slot >> 4, c4 = slot & 15;
            float4 v = W4[(size_t)row * (CC / 4) + (k0 >> 2) + c4];
            float* p = &sW[row * (KT + 1) + c4 * 4];
            p[0] = v.x; p[1] = v.y; p[2] = v.z; p[3] = v.w;
        }
        __syncthreads();
        const float* wrow = &sW[tid * (KT + 1)];
        const float* xk = &sx[k0];
#pragma unroll
        for (int kk = 0; kk < KT; kk++)
            acc = fmaf(xk[kk], wrow[kk], acc);
    }
    dst[tid] = acc;
}

__global__ __launch_bounds__(32) void k_rope_fix(const float* __restrict__ cosb,
                                                 const float* __restrict__ sinb,
                                                 const float* __restrict__ Wdq,
                                                 const float* __restrict__ Wdk)
{
    __shared__ float srow[128];
    int b = blockIdx.x;
    int cnt = g_fixcnt;
    if (cnt > FIXCAP) cnt = FIXCAP;
    if (b >= cnt) return;
    int e = g_fixlist[b];
    int qk = (e >> 20) & 1;
    int h = (e >> 16) & 15;
    int t = e & 0xFFFF;
    int lane = threadIdx.x;

    const float* src = (qk ? g_Kraw : g_Qraw) + (size_t)t * CC + h * DD;
    const float* Wd = qk ? Wdk : Wdq;

    float v0 = src[lane], v1 = src[lane + 32], v2 = src[lane + 64], v3 = src[lane + 96];
    float c0 = cosb[t * 64 + lane],      s0 = sinb[t * 64 + lane];
    float c1 = cosb[t * 64 + lane + 32], s1 = sinb[t * 64 + lane + 32];

    float r0 =  v0 * c0 + v2 * s0;
    float r1 =  v1 * c1 + v3 * s1;
    float r2 = -v0 * s0 + v2 * c0;
    float r3 = -v1 * s1 + v3 * c1;

    float ss = r0 * r0 + r1 * r1 + r2 * r2 + r3 * r3;
#pragma unroll
    for (int o = 16; o; o >>= 1) ss += __shfl_xor_sync(0xffffffffu, ss, o);
    float sc = rsqrtf(ss * (1.0f / 128.0f) + 1e-6f);
    r0 *= sc; r1 *= sc; r2 *= sc; r3 *= sc;

    srow[lane] = r0; srow[lane + 32] = r1;
    srow[lane + 64] = r2; srow[lane + 96] = r3;
    __syncwarp();
    {
        uint32_t* Hd = qk ? g_Knh : g_Qnh;
        uint32_t* Ld = qk ? g_Knl : g_Qnl;
        size_t base = ((size_t)h * TT + t) * (DD / 2);
        float a = srow[2 * lane], bb = srow[2 * lane + 1];
        float ha, la, hb, lb;
        split2(a, ha, la); split2(bb, hb, lb);
        Hd[base + lane] = pack2(ha, hb);
        Ld[base + lane] = pack2(la, lb);
        a = srow[64 + 2 * lane]; bb = srow[64 + 2 * lane + 1];
        split2(a, ha, la); split2(bb, hb, lb);
        Hd[base + 32 + lane] = pack2(ha, hb);
        Ld[base + 32 + lane] = pack2(la, lb);
    }

    int code = 0;
#pragma unroll
    for (int k = 0; k < NBITS; k++) {
        float z = r0 * Wd[k * DD + lane] + r1 * Wd[k * DD + lane + 32]
                + r2 * Wd[k * DD + lane + 64] + r3 * Wd[k * DD + lane + 96];
#pragma unroll
        for (int o = 16; o; o >>= 1) z += __shfl_xor_sync(0xffffffffu, z, o);
        float sg = 1.0f / (1.0f + expf(-z));
        int bit = (int)floorf(sg * 1.99f);
        code += bit << k;
    }
    if (lane == 0) (qk ? g_kc : g_qc)[h * TT + t] = code;
}

__global__ void k_transpose()
{
    __shared__ float tile[32][33];
    int x = blockIdx.x * 32 + threadIdx.x;
    int y = blockIdx.y * 32 + threadIdx.y;
#pragma unroll
    for (int i = 0; i < 32; i += 8)
        tile[threadIdx.y + i][threadIdx.x] = g_Vraw[(size_t)(y + i) * CC + x];
    __syncthreads();
    int tx = threadIdx.x, ty = threadIdx.y;
    if (tx < 16) {
#pragma unroll
        for (int i = 0; i < 32; i += 8) {
            int d = blockIdx.x * 32 + ty + i;
            float a = tile[2 * tx][ty + i];
            float b = tile[2 * tx + 1][ty + i];
            float ha, la, hb, lb;
            split2(a, ha, la); split2(b, hb, lb);
            size_t w = (size_t)d * (TT / 2) + blockIdx.y * 16 + tx;
            g_Vth[w] = pack2(ha, hb);
            g_Vtl[w] = pack2(la, lb);
        }
    }
}

extern "C" void kernel_launch(void* const* d_in, const int* in_sizes, int n_in,
                              void* d_out, int out_size)
{
    const float* x     = (const float*)d_in[0];
    const float* cosb  = (const float*)d_in[1];
    const float* sinb  = (const float*)d_in[2];
    const float* Wq    = (const float*)d_in[3];
    const float* Wk    = (const float*)d_in[4];
    const float* Wv    = (const float*)d_in[5];
    const float* Wproj = (const float*)d_in[6];
    const float* Wdq   = (const float*)d_in[7];
    const float* Wdk   = (const float*)d_in[8];
    float* out = (float*)d_out;

    static int s_attr_done = 0;
    if (!s_attr_done) {
        cudaFuncSetAttribute(k_qkv_tc,  cudaFuncAttributeMaxDynamicSharedMemorySize, GEMM_DSM);
        cudaFuncSetAttribute(k_proj_tc, cudaFuncAttributeMaxDynamicSharedMemorySize, GEMM_DSM);
        cudaFuncSetAttribute(k_flash,   cudaFuncAttributeMaxDynamicSharedMemorySize, FLASH_DSM);
        s_attr_done = 1;
    }

    k_zero_cnt<<<1, 1>>>();

    k_split_all<<<dim3(512, 5), 256>>>(x, Wq, Wk, Wv, Wproj);

    k_qkv_tc<<<dim3(16, 16, 3), 256, GEMM_DSM>>>();

    k_ropenorm<<<(2 * TT * HH) / 8, 256>>>(cosb, sinb, Wdq, Wdk);
    k_fix_raw<<<FIXCAP, 128>>>(x, Wq, Wk);
    k_rope_fix<<<FIXCAP, 32>>>(cosb, sinb, Wdq, Wdk);

    k_transpose<<<dim3(64, 64), dim3(32, 8)>>>();

    k_flash<<<dim3(16, 16), 256, FLASH_DSM>>>();

    k_proj_tc<<<dim3(16, 16, 1), 256, GEMM_DSM>>>(out);
}